// round 8
// baseline (speedup 1.0000x reference)
#include <cuda_runtime.h>
#include <cuda_bf16.h>
#include <math.h>
#include <stdint.h>

#define DIMC   768
#define HEADS  12
#define HD     64
#define BATCH  2
#define SEQ    2048
#define ROWS_TOT (BATCH * SEQ)      // 4096
#define QSCALE 0.125f

// ---------------------------------------------------------------------------
// Scratch (__device__ globals; 16B-aligned)
// ---------------------------------------------------------------------------
__device__ __align__(16) __nv_bfloat16 d_xhi[ROWS_TOT * DIMC];
__device__ __align__(16) __nv_bfloat16 d_xlo[ROWS_TOT * DIMC];
__device__ __align__(16) __nv_bfloat16 d_wqh[DIMC * DIMC];
__device__ __align__(16) __nv_bfloat16 d_wql[DIMC * DIMC];
__device__ __align__(16) __nv_bfloat16 d_wph[DIMC * DIMC];
__device__ __align__(16) __nv_bfloat16 d_wpl[DIMC * DIMC];
__device__ __align__(16) __nv_bfloat16 d_khi[BATCH * HEADS * SEQ * HD];
__device__ __align__(16) __nv_bfloat16 d_klo[BATCH * HEADS * SEQ * HD];
__device__ __align__(16) __nv_bfloat16 d_vthi[BATCH * HEADS * HD * SEQ];  // [bh][d][j]
__device__ __align__(16) __nv_bfloat16 d_vtlo[BATCH * HEADS * HD * SEQ];
__device__ __align__(16) __nv_bfloat16 d_qhi[BATCH * HEADS * SEQ * HD];
__device__ __align__(16) __nv_bfloat16 d_qlo[BATCH * HEADS * SEQ * HD];
__device__ __align__(16) __nv_bfloat16 d_ohi[ROWS_TOT * DIMC];
__device__ __align__(16) __nv_bfloat16 d_olo[ROWS_TOT * DIMC];

// ---------------------------------------------------------------------------
// Helpers
// ---------------------------------------------------------------------------
__device__ __forceinline__ uint32_t su32(const void* p) {
    uint32_t a;
    asm("{ .reg .u64 t; cvta.to.shared.u64 t, %1; cvt.u32.u64 %0, t; }"
        : "=r"(a) : "l"(p));
    return a;
}

__device__ __forceinline__ void cp16(uint32_t dst, const void* src) {
    asm volatile("cp.async.cg.shared.global [%0], [%1], 16;" :: "r"(dst), "l"(src));
}
#define CP_COMMIT() asm volatile("cp.async.commit_group;" ::: "memory")
#define CP_WAIT1()  asm volatile("cp.async.wait_group 1;" ::: "memory")
#define CP_WAIT0()  asm volatile("cp.async.wait_group 0;" ::: "memory")

#define LDSM_X4(r0, r1, r2, r3, addr) \
    asm volatile("ldmatrix.sync.aligned.m8n8.x4.shared.b16 {%0,%1,%2,%3}, [%4];" \
                 : "=r"(r0), "=r"(r1), "=r"(r2), "=r"(r3) : "r"(addr))

__device__ __forceinline__ void bsplit(float x, __nv_bfloat16& h, __nv_bfloat16& l) {
    h = __float2bfloat16(x);
    l = __float2bfloat16(x - __bfloat162float(h));
}

__device__ __forceinline__ uint32_t pk2(__nv_bfloat16 a, __nv_bfloat16 b) {
    __nv_bfloat162 t = __halves2bfloat162(a, b);
    return *reinterpret_cast<uint32_t*>(&t);
}

// D += A @ B  (m16n8k16, bf16 in, f32 acc), row.col
__device__ __forceinline__ void mma_bf16(float* c, const uint32_t* a, const uint32_t* b) {
    asm volatile(
        "mma.sync.aligned.m16n8k16.row.col.f32.bf16.bf16.f32 "
        "{%0,%1,%2,%3}, {%4,%5,%6,%7}, {%8,%9}, {%0,%1,%2,%3};"
        : "+f"(c[0]), "+f"(c[1]), "+f"(c[2]), "+f"(c[3])
        : "r"(a[0]), "r"(a[1]), "r"(a[2]), "r"(a[3]), "r"(b[0]), "r"(b[1]));
}

// ---------------------------------------------------------------------------
// Prep: fp32 -> bf16 (hi, lo) split
// ---------------------------------------------------------------------------
__global__ void split_kernel(const float* __restrict__ src, int which, int n4) {
    __nv_bfloat16 *hi, *lo;
    switch (which) {
        case 0: hi = d_xhi; lo = d_xlo; break;
        case 1: hi = d_wqh; lo = d_wql; break;
        case 2: hi = d_wph; lo = d_wpl; break;
        default: hi = d_khi; lo = d_klo; break;
    }
    int i = blockIdx.x * blockDim.x + threadIdx.x;
    if (i >= n4) return;
    float4 v = ((const float4*)src)[i];
    float vv[4] = {v.x, v.y, v.z, v.w};
    __nv_bfloat16 h[4], l[4];
#pragma unroll
    for (int j = 0; j < 4; j++) bsplit(vv[j], h[j], l[j]);
    *(uint2*)(hi + (size_t)i * 4) = make_uint2(pk2(h[0], h[1]), pk2(h[2], h[3]));
    *(uint2*)(lo + (size_t)i * 4) = make_uint2(pk2(l[0], l[1]), pk2(l[2], l[3]));
}

// V transpose + split: v[bh][j][d] -> vt[bh][d][j]
__global__ __launch_bounds__(256) void vtrans_kernel(const float* __restrict__ v) {
    __shared__ float t[64][65];
    int bh = blockIdx.y, j0 = blockIdx.x * 64;
    const float* src = v + ((size_t)bh * SEQ + j0) * HD;
    for (int idx = threadIdx.x; idx < 1024; idx += 256) {
        int r = idx >> 4, c4 = (idx & 15) * 4;
        float4 val = *(const float4*)(src + r * HD + c4);
        t[r][c4] = val.x; t[r][c4 + 1] = val.y;
        t[r][c4 + 2] = val.z; t[r][c4 + 3] = val.w;
    }
    __syncthreads();
    for (int idx = threadIdx.x; idx < 1024; idx += 256) {
        int d = idx >> 4, c4 = (idx & 15) * 4;
        __nv_bfloat16 h[4], l[4];
#pragma unroll
        for (int jj = 0; jj < 4; jj++) bsplit(t[c4 + jj][d], h[jj], l[jj]);
        size_t o = ((size_t)bh * HD + d) * SEQ + j0 + c4;
        *(uint2*)(d_vthi + o) = make_uint2(pk2(h[0], h[1]), pk2(h[2], h[3]));
        *(uint2*)(d_vtlo + o) = make_uint2(pk2(l[0], l[1]), pk2(l[2], l[3]));
    }
}

// ---------------------------------------------------------------------------
// GEMM via mma.sync + cp.async 2-stage: C[4096x768] = A @ W^T, split-bf16.
// BM=128 BN=128 BK=32; 8 warps = 4(m) x 2(n), warp tile 32x64. (unchanged)
// ---------------------------------------------------------------------------
#define GSTR 40
#define G_ARR_ELEM   (128 * GSTR)
#define G_STAGE_ELEM (4 * G_ARR_ELEM)
#define G_SMEM_BYTES (2 * G_STAGE_ELEM * 2)   // 81920

__global__ __launch_bounds__(256)
void gemm_mma(const float* __restrict__ bias, float* __restrict__ outp, int mode)
{
    extern __shared__ __nv_bfloat16 sm[];
    const uint32_t sb = su32(sm);

    const int tid = threadIdx.x, lane = tid & 31, wid = tid >> 5;
    const int wm = wid & 3, wn = wid >> 2;
    const int r4 = lane >> 2, q4 = lane & 3;
    const int m0 = blockIdx.y * 128, n0 = blockIdx.x * 128;

    const __nv_bfloat16* Ahg = (mode == 0) ? d_xhi : d_ohi;
    const __nv_bfloat16* Alg = (mode == 0) ? d_xlo : d_olo;
    const __nv_bfloat16* Bhg = (mode == 0) ? d_wqh : d_wph;
    const __nv_bfloat16* Blg = (mode == 0) ? d_wql : d_wpl;

    auto issue = [&](int kb, int s) {
        const int k0 = kb * 32;
        const uint32_t so = sb + (uint32_t)(s * G_STAGE_ELEM) * 2;
        for (int id = tid; id < 512; id += 256) {
            int r = id >> 2, sg = id & 3;
            uint32_t d0 = so + (uint32_t)(r * GSTR + sg * 8) * 2;
            size_t ga = (size_t)(m0 + r) * DIMC + k0 + sg * 8;
            size_t gb = (size_t)(n0 + r) * DIMC + k0 + sg * 8;
            cp16(d0,                       Ahg + ga);
            cp16(d0 + G_ARR_ELEM * 2,      Alg + ga);
            cp16(d0 + 2 * G_ARR_ELEM * 2,  Bhg + gb);
            cp16(d0 + 3 * G_ARR_ELEM * 2,  Blg + gb);
        }
    };

    float c[2][8][4];
#pragma unroll
    for (int i = 0; i < 2; i++)
#pragma unroll
        for (int j = 0; j < 8; j++)
#pragma unroll
            for (int e = 0; e < 4; e++) c[i][j][e] = 0.f;

    issue(0, 0);
    CP_COMMIT();

    const int NKB = DIMC / 32;   // 24
    for (int kb = 0; kb < NKB; kb++) {
        if (kb + 1 < NKB) {
            issue(kb + 1, (kb + 1) & 1);
            CP_COMMIT();
            CP_WAIT1();
        } else {
            CP_WAIT0();
        }
        __syncthreads();

        const __nv_bfloat16* Ah = sm + (kb & 1) * G_STAGE_ELEM;
        const __nv_bfloat16* Al = Ah + G_ARR_ELEM;
        const __nv_bfloat16* Bh = Ah + 2 * G_ARR_ELEM;
        const __nv_bfloat16* Bl = Ah + 3 * G_ARR_ELEM;

#pragma unroll
        for (int ks = 0; ks < 2; ks++) {
            const int ca = ks * 16 + q4 * 2;
            uint32_t ah[2][4], al2[2][4];
#pragma unroll
            for (int i = 0; i < 2; i++) {
                int rb = wm * 32 + i * 16 + r4;
                ah[i][0] = *(const uint32_t*)(Ah + rb * GSTR + ca);
                ah[i][1] = *(const uint32_t*)(Ah + (rb + 8) * GSTR + ca);
                ah[i][2] = *(const uint32_t*)(Ah + rb * GSTR + ca + 8);
                ah[i][3] = *(const uint32_t*)(Ah + (rb + 8) * GSTR + ca + 8);
                al2[i][0] = *(const uint32_t*)(Al + rb * GSTR + ca);
                al2[i][1] = *(const uint32_t*)(Al + (rb + 8) * GSTR + ca);
                al2[i][2] = *(const uint32_t*)(Al + rb * GSTR + ca + 8);
                al2[i][3] = *(const uint32_t*)(Al + (rb + 8) * GSTR + ca + 8);
            }
#pragma unroll
            for (int j = 0; j < 8; j++) {
                int nb = wn * 64 + j * 8 + r4;
                uint32_t bh2[2], bl2[2];
                bh2[0] = *(const uint32_t*)(Bh + nb * GSTR + ca);
                bh2[1] = *(const uint32_t*)(Bh + nb * GSTR + ca + 8);
                bl2[0] = *(const uint32_t*)(Bl + nb * GSTR + ca);
                bl2[1] = *(const uint32_t*)(Bl + nb * GSTR + ca + 8);
#pragma unroll
                for (int i = 0; i < 2; i++) {
                    mma_bf16(c[i][j], ah[i], bh2);
                    mma_bf16(c[i][j], al2[i], bh2);
                    mma_bf16(c[i][j], ah[i], bl2);
                }
            }
        }
        __syncthreads();
    }

    // Epilogue
#pragma unroll
    for (int i = 0; i < 2; i++) {
        int mrow = m0 + wm * 32 + i * 16 + r4;
#pragma unroll
        for (int j = 0; j < 8; j++) {
            int col = n0 + wn * 64 + j * 8 + q4 * 2;
            if (mode == 0) {
                int head = col >> 6, d = col & 63;
#pragma unroll
                for (int h2 = 0; h2 < 2; h2++) {
                    int m = mrow + h2 * 8;
                    int b = m >> 11, seqq = m & 2047;
                    float f0 = c[i][j][h2 * 2] * QSCALE;
                    float f1 = c[i][j][h2 * 2 + 1] * QSCALE;
                    __nv_bfloat16 h0, l0, h1, l1;
                    bsplit(f0, h0, l0); bsplit(f1, h1, l1);
                    size_t off = ((size_t)(b * HEADS + head) * SEQ + seqq) * HD + d;
                    *(uint32_t*)(d_qhi + off) = pk2(h0, h1);
                    *(uint32_t*)(d_qlo + off) = pk2(l0, l1);
                }
            } else {
                float2 bv = *(const float2*)(bias + col);
#pragma unroll
                for (int h2 = 0; h2 < 2; h2++) {
                    int m = mrow + h2 * 8;
                    float2 v;
                    v.x = c[i][j][h2 * 2] + bv.x;
                    v.y = c[i][j][h2 * 2 + 1] + bv.y;
                    *(float2*)(outp + (size_t)m * DIMC + col) = v;
                }
            }
        }
    }
}

// ---------------------------------------------------------------------------
// Flash attention: mma.sync + cp.async 2-stage + ldmatrix fragment loads.
// 1 CTA per (b,h,128-q tile); 8 warps x 16 query rows; 32 chunks of 64 keys.
// Q fragments loaded straight from gmem (no Q smem).
// ---------------------------------------------------------------------------
#define FSTR 72
#define F_ARR_ELEM   (64 * FSTR)
#define F_STAGE_ELEM (4 * F_ARR_ELEM)
#define F_SMEM_BYTES (2 * F_STAGE_ELEM * 2)   // 73728

__global__ __launch_bounds__(256)
void flash_mma()
{
    extern __shared__ __nv_bfloat16 fsm[];
    const uint32_t sb = su32(fsm);

    const int tid = threadIdx.x, lane = tid & 31, wid = tid >> 5;
    const int r4 = lane >> 2, q4 = lane & 3;
    const int grp = lane >> 3, lrow = lane & 7;
    const int qt = blockIdx.x, head = blockIdx.y, b = blockIdx.z;
    const int bh = b * HEADS + head;

    const __nv_bfloat16* khg = d_khi + (size_t)bh * SEQ * HD;
    const __nv_bfloat16* klg = d_klo + (size_t)bh * SEQ * HD;
    const __nv_bfloat16* vhg = d_vthi + (size_t)bh * HD * SEQ;
    const __nv_bfloat16* vlg = d_vtlo + (size_t)bh * HD * SEQ;

    auto issue = [&](int c, int s) {
        const uint32_t so = sb + (uint32_t)(s * F_STAGE_ELEM) * 2;
        const __nv_bfloat16* kh = khg + (size_t)c * 64 * HD;
        const __nv_bfloat16* kl = klg + (size_t)c * 64 * HD;
        const __nv_bfloat16* vh = vhg + c * 64;
        const __nv_bfloat16* vl = vlg + c * 64;
        for (int id = tid; id < 512; id += 256) {
            int r = id >> 3, sg = id & 7;
            uint32_t d0 = so + (uint32_t)(r * FSTR + sg * 8) * 2;
            cp16(d0,                      kh + r * HD + sg * 8);
            cp16(d0 + F_ARR_ELEM * 2,     kl + r * HD + sg * 8);
            cp16(d0 + 2 * F_ARR_ELEM * 2, vh + (size_t)r * SEQ + sg * 8);
            cp16(d0 + 3 * F_ARR_ELEM * 2, vl + (size_t)r * SEQ + sg * 8);
        }
    };

    issue(0, 0);
    CP_COMMIT();

    // Q fragments directly from gmem (once)
    uint32_t qfh[4][4], qfl[4][4];
    {
        const __nv_bfloat16* qhg = d_qhi + ((size_t)bh * SEQ + qt * 128) * HD;
        const __nv_bfloat16* qlg = d_qlo + ((size_t)bh * SEQ + qt * 128) * HD;
        const int rb = wid * 16 + r4;
#pragma unroll
        for (int ks = 0; ks < 4; ks++) {
            const int ca = ks * 16 + q4 * 2;
            qfh[ks][0] = *(const uint32_t*)(qhg + rb * HD + ca);
            qfh[ks][1] = *(const uint32_t*)(qhg + (rb + 8) * HD + ca);
            qfh[ks][2] = *(const uint32_t*)(qhg + rb * HD + ca + 8);
            qfh[ks][3] = *(const uint32_t*)(qhg + (rb + 8) * HD + ca + 8);
            qfl[ks][0] = *(const uint32_t*)(qlg + rb * HD + ca);
            qfl[ks][1] = *(const uint32_t*)(qlg + (rb + 8) * HD + ca);
            qfl[ks][2] = *(const uint32_t*)(qlg + rb * HD + ca + 8);
            qfl[ks][3] = *(const uint32_t*)(qlg + (rb + 8) * HD + ca + 8);
        }
    }

    float o[8][4];
#pragma unroll
    for (int j = 0; j < 8; j++)
#pragma unroll
        for (int e = 0; e < 4; e++) o[j][e] = 0.f;
    float lsum0 = 0.f, lsum1 = 0.f;

    // ldmatrix lane-base offsets (within a stage):
    //  K: grp0 -> Kh col+0, grp1 -> Kh col+8, grp2 -> Kl col+0, grp3 -> Kl col+8
    const uint32_t kgrp = ((grp >> 1) ? F_ARR_ELEM * 2u : 0u) + (grp & 1) * 16u
                        + (uint32_t)lrow * FSTR * 2u;
    const uint32_t vgrp = 2u * F_ARR_ELEM * 2u + kgrp;

    union { float f[8][4]; uint32_t u[8][4]; } S;

    const int NC = SEQ / 64;   // 32
    for (int c = 0; c < NC; c++) {
        if (c + 1 < NC) {
            issue(c + 1, (c + 1) & 1);
            CP_COMMIT();
            CP_WAIT1();
        } else {
            CP_WAIT0();
        }
        __syncthreads();

        const uint32_t stage = sb + (uint32_t)((c & 1) * F_STAGE_ELEM) * 2;
        const uint32_t kbase = stage + kgrp;
        const uint32_t vbase = stage + vgrp;

        // S = Q K^T
#pragma unroll
        for (int j = 0; j < 8; j++)
#pragma unroll
            for (int e = 0; e < 4; e++) S.f[j][e] = 0.f;

#pragma unroll
        for (int ks = 0; ks < 4; ks++) {
#pragma unroll
            for (int j = 0; j < 8; j++) {
                uint32_t kb2[4];
                LDSM_X4(kb2[0], kb2[1], kb2[2], kb2[3],
                        kbase + (uint32_t)(ks * 32 + j * (8 * FSTR * 2)));
                mma_bf16(S.f[j], qfh[ks], kb2);       // qh * kh
                mma_bf16(S.f[j], qfl[ks], kb2);       // ql * kh
                mma_bf16(S.f[j], qfh[ks], kb2 + 2);   // qh * kl
            }
        }

        // exp + row sums
        float rs0 = 0.f, rs1 = 0.f;
#pragma unroll
        for (int j = 0; j < 8; j++) {
#pragma unroll
            for (int e = 0; e < 4; e++) S.f[j][e] = __expf(S.f[j][e]);
            rs0 += S.f[j][0] + S.f[j][1];
            rs1 += S.f[j][2] + S.f[j][3];
        }
        rs0 += __shfl_xor_sync(0xffffffffu, rs0, 1);
        rs0 += __shfl_xor_sync(0xffffffffu, rs0, 2);
        rs1 += __shfl_xor_sync(0xffffffffu, rs1, 1);
        rs1 += __shfl_xor_sync(0xffffffffu, rs1, 2);
        lsum0 += rs0;
        lsum1 += rs1;

        // Pack P hi/lo A-fragments in place over dead S registers:
        // hi[t] -> S.u[2t][0..3], lo[t] -> S.u[2t+1][0..3]
#pragma unroll
        for (int t = 0; t < 4; t++) {
            float a0 = S.f[2 * t][0], a1 = S.f[2 * t][1];
            float a2 = S.f[2 * t][2], a3 = S.f[2 * t][3];
            float b0 = S.f[2 * t + 1][0], b1 = S.f[2 * t + 1][1];
            float b2 = S.f[2 * t + 1][2], b3 = S.f[2 * t + 1][3];
            __nv_bfloat16 h0, l0, h1, l1, h2, l2, h3, l3;
            bsplit(a0, h0, l0); bsplit(a1, h1, l1);
            bsplit(a2, h2, l2); bsplit(a3, h3, l3);
            S.u[2 * t][0] = pk2(h0, h1);
            S.u[2 * t][1] = pk2(h2, h3);
            S.u[2 * t + 1][0] = pk2(l0, l1);
            S.u[2 * t + 1][1] = pk2(l2, l3);
            bsplit(b0, h0, l0); bsplit(b1, h1, l1);
            bsplit(b2, h2, l2); bsplit(b3, h3, l3);
            S.u[2 * t][2] = pk2(h0, h1);
            S.u[2 * t][3] = pk2(h2, h3);
            S.u[2 * t + 1][2] = pk2(l0, l1);
            S.u[2 * t + 1][3] = pk2(l2, l3);
        }

        // O += P V
#pragma unroll
        for (int t = 0; t < 4; t++) {
#pragma unroll
            for (int j = 0; j < 8; j++) {
                uint32_t vb2[4];
                LDSM_X4(vb2[0], vb2[1], vb2[2], vb2[3],
                        vbase + (uint32_t)(t * 32 + j * (8 * FSTR * 2)));
                mma_bf16(o[j], S.u[2 * t], vb2);          // ph * vh
                mma_bf16(o[j], S.u[2 * t + 1], vb2);      // pl * vh
                mma_bf16(o[j], S.u[2 * t], vb2 + 2);      // ph * vl
            }
        }
        __syncthreads();
    }

    // Normalize + split-store to d_ohi/d_olo in [B, N, 768]
    const float inv0 = 1.0f / lsum0, inv1 = 1.0f / lsum1;
    const int row0 = qt * 128 + wid * 16 + r4;
#pragma unroll
    for (int j = 0; j < 8; j++) {
        int col = head * HD + j * 8 + q4 * 2;
        __nv_bfloat16 h0, l0, h1, l1;
        float f0 = o[j][0] * inv0, f1 = o[j][1] * inv0;
        bsplit(f0, h0, l0); bsplit(f1, h1, l1);
        size_t off = ((size_t)(b * SEQ + row0)) * DIMC + col;
        *(uint32_t*)(d_ohi + off) = pk2(h0, h1);
        *(uint32_t*)(d_olo + off) = pk2(l0, l1);
        float f2 = o[j][2] * inv1, f3 = o[j][3] * inv1;
        bsplit(f2, h0, l0); bsplit(f3, h1, l1);
        off = ((size_t)(b * SEQ + row0 + 8)) * DIMC + col;
        *(uint32_t*)(d_ohi + off) = pk2(h0, h1);
        *(uint32_t*)(d_olo + off) = pk2(l0, l1);
    }
}

// ---------------------------------------------------------------------------
extern "C" void kernel_launch(void* const* d_in, const int* in_sizes, int n_in,
                              void* d_out, int out_size)
{
    const float* x  = (const float*)d_in[0];
    const float* kk = (const float*)d_in[1];
    const float* vv = (const float*)d_in[2];
    const float* wq = (const float*)d_in[3];
    const float* wp = (const float*)d_in[4];
    const float* bp = (const float*)d_in[5];
    float* out = (float*)d_out;

    cudaFuncSetAttribute(gemm_mma, cudaFuncAttributeMaxDynamicSharedMemorySize, G_SMEM_BYTES);
    cudaFuncSetAttribute(flash_mma, cudaFuncAttributeMaxDynamicSharedMemorySize, F_SMEM_BYTES);

    const int n4_big = ROWS_TOT * DIMC / 4;   // 786432
    const int n4_w   = DIMC * DIMC / 4;       // 147456

    split_kernel<<<(n4_big + 255) / 256, 256>>>(x,  0, n4_big);
    split_kernel<<<(n4_w   + 255) / 256, 256>>>(wq, 1, n4_w);
    split_kernel<<<(n4_w   + 255) / 256, 256>>>(wp, 2, n4_w);
    split_kernel<<<(n4_big + 255) / 256, 256>>>(kk, 3, n4_big);
    vtrans_kernel<<<dim3(SEQ / 64, BATCH * HEADS), 256>>>(vv);

    gemm_mma<<<dim3(DIMC / 128, ROWS_TOT / 128), 256, G_SMEM_BYTES>>>(nullptr, nullptr, 0);
    flash_mma<<<dim3(SEQ / 128, HEADS, BATCH), 256, F_SMEM_BYTES>>>();
    gemm_mma<<<dim3(DIMC / 128, ROWS_TOT / 128), 256, G_SMEM_BYTES>>>(bp, out, 1);
}

// round 9
// speedup vs baseline: 1.0533x; 1.0533x over previous
#include <cuda_runtime.h>
#include <cuda_bf16.h>
#include <math.h>
#include <stdint.h>

#define DIMC   768
#define HEADS  12
#define HD     64
#define BATCH  2
#define SEQ    2048
#define ROWS_TOT (BATCH * SEQ)      // 4096
#define QSCALE 0.125f

// ---------------------------------------------------------------------------
// Scratch (__device__ globals; 16B-aligned)
// ---------------------------------------------------------------------------
__device__ __align__(16) __nv_bfloat16 d_xhi[ROWS_TOT * DIMC];
__device__ __align__(16) __nv_bfloat16 d_xlo[ROWS_TOT * DIMC];
__device__ __align__(16) __nv_bfloat16 d_wqh[DIMC * DIMC];
__device__ __align__(16) __nv_bfloat16 d_wql[DIMC * DIMC];
__device__ __align__(16) __nv_bfloat16 d_wph[DIMC * DIMC];
__device__ __align__(16) __nv_bfloat16 d_wpl[DIMC * DIMC];
__device__ __align__(16) __nv_bfloat16 d_khi[BATCH * HEADS * SEQ * HD];
__device__ __align__(16) __nv_bfloat16 d_klo[BATCH * HEADS * SEQ * HD];
__device__ __align__(16) __nv_bfloat16 d_vthi[BATCH * HEADS * HD * SEQ];  // [bh][d][j]
__device__ __align__(16) __nv_bfloat16 d_vtlo[BATCH * HEADS * HD * SEQ];
__device__ __align__(16) __nv_bfloat16 d_qhi[BATCH * HEADS * SEQ * HD];
__device__ __align__(16) __nv_bfloat16 d_qlo[BATCH * HEADS * SEQ * HD];
__device__ __align__(16) __nv_bfloat16 d_ohi[ROWS_TOT * DIMC];
__device__ __align__(16) __nv_bfloat16 d_olo[ROWS_TOT * DIMC];

// ---------------------------------------------------------------------------
// Helpers
// ---------------------------------------------------------------------------
__device__ __forceinline__ uint32_t su32(const void* p) {
    uint32_t a;
    asm("{ .reg .u64 t; cvta.to.shared.u64 t, %1; cvt.u32.u64 %0, t; }"
        : "=r"(a) : "l"(p));
    return a;
}

__device__ __forceinline__ void cp16(uint32_t dst, const void* src) {
    asm volatile("cp.async.cg.shared.global [%0], [%1], 16;" :: "r"(dst), "l"(src));
}
#define CP_COMMIT() asm volatile("cp.async.commit_group;" ::: "memory")
#define CP_WAIT1()  asm volatile("cp.async.wait_group 1;" ::: "memory")
#define CP_WAIT0()  asm volatile("cp.async.wait_group 0;" ::: "memory")

#define LDSM_X4(r0, r1, r2, r3, addr) \
    asm volatile("ldmatrix.sync.aligned.m8n8.x4.shared.b16 {%0,%1,%2,%3}, [%4];" \
                 : "=r"(r0), "=r"(r1), "=r"(r2), "=r"(r3) : "r"(addr))

__device__ __forceinline__ void bsplit(float x, __nv_bfloat16& h, __nv_bfloat16& l) {
    h = __float2bfloat16(x);
    l = __float2bfloat16(x - __bfloat162float(h));
}

__device__ __forceinline__ uint32_t pk2(__nv_bfloat16 a, __nv_bfloat16 b) {
    __nv_bfloat162 t = __halves2bfloat162(a, b);
    return *reinterpret_cast<uint32_t*>(&t);
}

// D += A @ B  (m16n8k16, bf16 in, f32 acc), row.col
__device__ __forceinline__ void mma_bf16(float* c, const uint32_t* a, const uint32_t* b) {
    asm volatile(
        "mma.sync.aligned.m16n8k16.row.col.f32.bf16.bf16.f32 "
        "{%0,%1,%2,%3}, {%4,%5,%6,%7}, {%8,%9}, {%0,%1,%2,%3};"
        : "+f"(c[0]), "+f"(c[1]), "+f"(c[2]), "+f"(c[3])
        : "r"(a[0]), "r"(a[1]), "r"(a[2]), "r"(a[3]), "r"(b[0]), "r"(b[1]));
}

// ---------------------------------------------------------------------------
// Prep: fp32 -> bf16 (hi, lo) split
// ---------------------------------------------------------------------------
__global__ void split_kernel(const float* __restrict__ src, int which, int n4) {
    __nv_bfloat16 *hi, *lo;
    switch (which) {
        case 0: hi = d_xhi; lo = d_xlo; break;
        case 1: hi = d_wqh; lo = d_wql; break;
        case 2: hi = d_wph; lo = d_wpl; break;
        default: hi = d_khi; lo = d_klo; break;
    }
    int i = blockIdx.x * blockDim.x + threadIdx.x;
    if (i >= n4) return;
    float4 v = ((const float4*)src)[i];
    float vv[4] = {v.x, v.y, v.z, v.w};
    __nv_bfloat16 h[4], l[4];
#pragma unroll
    for (int j = 0; j < 4; j++) bsplit(vv[j], h[j], l[j]);
    *(uint2*)(hi + (size_t)i * 4) = make_uint2(pk2(h[0], h[1]), pk2(h[2], h[3]));
    *(uint2*)(lo + (size_t)i * 4) = make_uint2(pk2(l[0], l[1]), pk2(l[2], l[3]));
}

// V transpose + split: v[bh][j][d] -> vt[bh][d][j]
__global__ __launch_bounds__(256) void vtrans_kernel(const float* __restrict__ v) {
    __shared__ float t[64][65];
    int bh = blockIdx.y, j0 = blockIdx.x * 64;
    const float* src = v + ((size_t)bh * SEQ + j0) * HD;
    for (int idx = threadIdx.x; idx < 1024; idx += 256) {
        int r = idx >> 4, c4 = (idx & 15) * 4;
        float4 val = *(const float4*)(src + r * HD + c4);
        t[r][c4] = val.x; t[r][c4 + 1] = val.y;
        t[r][c4 + 2] = val.z; t[r][c4 + 3] = val.w;
    }
    __syncthreads();
    for (int idx = threadIdx.x; idx < 1024; idx += 256) {
        int d = idx >> 4, c4 = (idx & 15) * 4;
        __nv_bfloat16 h[4], l[4];
#pragma unroll
        for (int jj = 0; jj < 4; jj++) bsplit(t[c4 + jj][d], h[jj], l[jj]);
        size_t o = ((size_t)bh * HD + d) * SEQ + j0 + c4;
        *(uint2*)(d_vthi + o) = make_uint2(pk2(h[0], h[1]), pk2(h[2], h[3]));
        *(uint2*)(d_vtlo + o) = make_uint2(pk2(l[0], l[1]), pk2(l[2], l[3]));
    }
}

// ---------------------------------------------------------------------------
// GEMM via mma.sync + cp.async 2-stage: C[4096x768] = A @ W^T, split-bf16.
// BM=128 BN=128 BK=32; 8 warps = 4(m) x 2(n), warp tile 32x64.
// ---------------------------------------------------------------------------
#define GSTR 40
#define G_ARR_ELEM   (128 * GSTR)
#define G_STAGE_ELEM (4 * G_ARR_ELEM)
#define G_SMEM_BYTES (2 * G_STAGE_ELEM * 2)   // 81920

__global__ __launch_bounds__(256, 2)
void gemm_mma(const float* __restrict__ bias, float* __restrict__ outp, int mode)
{
    extern __shared__ __nv_bfloat16 sm[];
    const uint32_t sb = su32(sm);

    const int tid = threadIdx.x, lane = tid & 31, wid = tid >> 5;
    const int wm = wid & 3, wn = wid >> 2;
    const int r4 = lane >> 2, q4 = lane & 3;
    const int m0 = blockIdx.y * 128, n0 = blockIdx.x * 128;

    const __nv_bfloat16* Ahg = (mode == 0) ? d_xhi : d_ohi;
    const __nv_bfloat16* Alg = (mode == 0) ? d_xlo : d_olo;
    const __nv_bfloat16* Bhg = (mode == 0) ? d_wqh : d_wph;
    const __nv_bfloat16* Blg = (mode == 0) ? d_wql : d_wpl;

    auto issue = [&](int kb, int s) {
        const int k0 = kb * 32;
        const uint32_t so = sb + (uint32_t)(s * G_STAGE_ELEM) * 2;
        for (int id = tid; id < 512; id += 256) {
            int r = id >> 2, sg = id & 3;
            uint32_t d0 = so + (uint32_t)(r * GSTR + sg * 8) * 2;
            size_t ga = (size_t)(m0 + r) * DIMC + k0 + sg * 8;
            size_t gb = (size_t)(n0 + r) * DIMC + k0 + sg * 8;
            cp16(d0,                       Ahg + ga);
            cp16(d0 + G_ARR_ELEM * 2,      Alg + ga);
            cp16(d0 + 2 * G_ARR_ELEM * 2,  Bhg + gb);
            cp16(d0 + 3 * G_ARR_ELEM * 2,  Blg + gb);
        }
    };

    float c[2][8][4];
#pragma unroll
    for (int i = 0; i < 2; i++)
#pragma unroll
        for (int j = 0; j < 8; j++)
#pragma unroll
            for (int e = 0; e < 4; e++) c[i][j][e] = 0.f;

    issue(0, 0);
    CP_COMMIT();

    const int NKB = DIMC / 32;   // 24
    for (int kb = 0; kb < NKB; kb++) {
        if (kb + 1 < NKB) {
            issue(kb + 1, (kb + 1) & 1);
            CP_COMMIT();
            CP_WAIT1();
        } else {
            CP_WAIT0();
        }
        __syncthreads();

        const __nv_bfloat16* Ah = sm + (kb & 1) * G_STAGE_ELEM;
        const __nv_bfloat16* Al = Ah + G_ARR_ELEM;
        const __nv_bfloat16* Bh = Ah + 2 * G_ARR_ELEM;
        const __nv_bfloat16* Bl = Ah + 3 * G_ARR_ELEM;

#pragma unroll
        for (int ks = 0; ks < 2; ks++) {
            const int ca = ks * 16 + q4 * 2;
            uint32_t ah[2][4], al2[2][4];
#pragma unroll
            for (int i = 0; i < 2; i++) {
                int rb = wm * 32 + i * 16 + r4;
                ah[i][0] = *(const uint32_t*)(Ah + rb * GSTR + ca);
                ah[i][1] = *(const uint32_t*)(Ah + (rb + 8) * GSTR + ca);
                ah[i][2] = *(const uint32_t*)(Ah + rb * GSTR + ca + 8);
                ah[i][3] = *(const uint32_t*)(Ah + (rb + 8) * GSTR + ca + 8);
                al2[i][0] = *(const uint32_t*)(Al + rb * GSTR + ca);
                al2[i][1] = *(const uint32_t*)(Al + (rb + 8) * GSTR + ca);
                al2[i][2] = *(const uint32_t*)(Al + rb * GSTR + ca + 8);
                al2[i][3] = *(const uint32_t*)(Al + (rb + 8) * GSTR + ca + 8);
            }
#pragma unroll
            for (int j = 0; j < 8; j++) {
                int nb = wn * 64 + j * 8 + r4;
                uint32_t bh2[2], bl2[2];
                bh2[0] = *(const uint32_t*)(Bh + nb * GSTR + ca);
                bh2[1] = *(const uint32_t*)(Bh + nb * GSTR + ca + 8);
                bl2[0] = *(const uint32_t*)(Bl + nb * GSTR + ca);
                bl2[1] = *(const uint32_t*)(Bl + nb * GSTR + ca + 8);
#pragma unroll
                for (int i = 0; i < 2; i++) {
                    mma_bf16(c[i][j], ah[i], bh2);
                    mma_bf16(c[i][j], al2[i], bh2);
                    mma_bf16(c[i][j], ah[i], bl2);
                }
            }
        }
        __syncthreads();
    }

    // Epilogue
#pragma unroll
    for (int i = 0; i < 2; i++) {
        int mrow = m0 + wm * 32 + i * 16 + r4;
#pragma unroll
        for (int j = 0; j < 8; j++) {
            int col = n0 + wn * 64 + j * 8 + q4 * 2;
            if (mode == 0) {
                int head = col >> 6, d = col & 63;
#pragma unroll
                for (int h2 = 0; h2 < 2; h2++) {
                    int m = mrow + h2 * 8;
                    int b = m >> 11, seqq = m & 2047;
                    float f0 = c[i][j][h2 * 2] * QSCALE;
                    float f1 = c[i][j][h2 * 2 + 1] * QSCALE;
                    __nv_bfloat16 h0, l0, h1, l1;
                    bsplit(f0, h0, l0); bsplit(f1, h1, l1);
                    size_t off = ((size_t)(b * HEADS + head) * SEQ + seqq) * HD + d;
                    *(uint32_t*)(d_qhi + off) = pk2(h0, h1);
                    *(uint32_t*)(d_qlo + off) = pk2(l0, l1);
                }
            } else {
                float2 bv = *(const float2*)(bias + col);
#pragma unroll
                for (int h2 = 0; h2 < 2; h2++) {
                    int m = mrow + h2 * 8;
                    float2 v;
                    v.x = c[i][j][h2 * 2] + bv.x;
                    v.y = c[i][j][h2 * 2 + 1] + bv.y;
                    *(float2*)(outp + (size_t)m * DIMC + col) = v;
                }
            }
        }
    }
}

// ---------------------------------------------------------------------------
// Flash attention: mma.sync + cp.async 2-stage + ldmatrix fragment loads.
// 1 CTA per (b,h,128-q tile); 8 warps x 16 query rows; 32 chunks of 64 keys.
// Q fragments loaded straight from gmem (no Q smem). 2 CTAs/SM forced.
// ---------------------------------------------------------------------------
#define FSTR 72
#define F_ARR_ELEM   (64 * FSTR)
#define F_STAGE_ELEM (4 * F_ARR_ELEM)
#define F_SMEM_BYTES (2 * F_STAGE_ELEM * 2)   // 73728

__global__ __launch_bounds__(256, 2)
void flash_mma()
{
    extern __shared__ __nv_bfloat16 fsm[];
    const uint32_t sb = su32(fsm);

    const int tid = threadIdx.x, lane = tid & 31, wid = tid >> 5;
    const int r4 = lane >> 2, q4 = lane & 3;
    const int grp = lane >> 3, lrow = lane & 7;
    const int qt = blockIdx.x, head = blockIdx.y, b = blockIdx.z;
    const int bh = b * HEADS + head;

    const __nv_bfloat16* khg = d_khi + (size_t)bh * SEQ * HD;
    const __nv_bfloat16* klg = d_klo + (size_t)bh * SEQ * HD;
    const __nv_bfloat16* vhg = d_vthi + (size_t)bh * HD * SEQ;
    const __nv_bfloat16* vlg = d_vtlo + (size_t)bh * HD * SEQ;

    auto issue = [&](int c, int s) {
        const uint32_t so = sb + (uint32_t)(s * F_STAGE_ELEM) * 2;
        const __nv_bfloat16* kh = khg + (size_t)c * 64 * HD;
        const __nv_bfloat16* kl = klg + (size_t)c * 64 * HD;
        const __nv_bfloat16* vh = vhg + c * 64;
        const __nv_bfloat16* vl = vlg + c * 64;
        for (int id = tid; id < 512; id += 256) {
            int r = id >> 3, sg = id & 7;
            uint32_t d0 = so + (uint32_t)(r * FSTR + sg * 8) * 2;
            cp16(d0,                      kh + r * HD + sg * 8);
            cp16(d0 + F_ARR_ELEM * 2,     kl + r * HD + sg * 8);
            cp16(d0 + 2 * F_ARR_ELEM * 2, vh + (size_t)r * SEQ + sg * 8);
            cp16(d0 + 3 * F_ARR_ELEM * 2, vl + (size_t)r * SEQ + sg * 8);
        }
    };

    issue(0, 0);
    CP_COMMIT();

    // Q fragments directly from gmem (once)
    uint32_t qfh[4][4], qfl[4][4];
    {
        const __nv_bfloat16* qhg = d_qhi + ((size_t)bh * SEQ + qt * 128) * HD;
        const __nv_bfloat16* qlg = d_qlo + ((size_t)bh * SEQ + qt * 128) * HD;
        const int rb = wid * 16 + r4;
#pragma unroll
        for (int ks = 0; ks < 4; ks++) {
            const int ca = ks * 16 + q4 * 2;
            qfh[ks][0] = *(const uint32_t*)(qhg + rb * HD + ca);
            qfh[ks][1] = *(const uint32_t*)(qhg + (rb + 8) * HD + ca);
            qfh[ks][2] = *(const uint32_t*)(qhg + rb * HD + ca + 8);
            qfh[ks][3] = *(const uint32_t*)(qhg + (rb + 8) * HD + ca + 8);
            qfl[ks][0] = *(const uint32_t*)(qlg + rb * HD + ca);
            qfl[ks][1] = *(const uint32_t*)(qlg + (rb + 8) * HD + ca);
            qfl[ks][2] = *(const uint32_t*)(qlg + rb * HD + ca + 8);
            qfl[ks][3] = *(const uint32_t*)(qlg + (rb + 8) * HD + ca + 8);
        }
    }

    float o[8][4];
#pragma unroll
    for (int j = 0; j < 8; j++)
#pragma unroll
        for (int e = 0; e < 4; e++) o[j][e] = 0.f;
    float lsum0 = 0.f, lsum1 = 0.f;

    // ldmatrix lane-base offsets (within a stage):
    //  K: grp0 -> Kh col+0, grp1 -> Kh col+8, grp2 -> Kl col+0, grp3 -> Kl col+8
    const uint32_t kgrp = ((grp >> 1) ? F_ARR_ELEM * 2u : 0u) + (grp & 1) * 16u
                        + (uint32_t)lrow * FSTR * 2u;
    const uint32_t vgrp = 2u * F_ARR_ELEM * 2u + kgrp;

    union { float f[8][4]; uint32_t u[8][4]; } S;

    const int NC = SEQ / 64;   // 32
    for (int c = 0; c < NC; c++) {
        if (c + 1 < NC) {
            issue(c + 1, (c + 1) & 1);
            CP_COMMIT();
            CP_WAIT1();
        } else {
            CP_WAIT0();
        }
        __syncthreads();

        const uint32_t stage = sb + (uint32_t)((c & 1) * F_STAGE_ELEM) * 2;
        const uint32_t kbase = stage + kgrp;
        const uint32_t vbase = stage + vgrp;

        // S = Q K^T
#pragma unroll
        for (int j = 0; j < 8; j++)
#pragma unroll
            for (int e = 0; e < 4; e++) S.f[j][e] = 0.f;

#pragma unroll
        for (int ks = 0; ks < 4; ks++) {
#pragma unroll
            for (int j = 0; j < 8; j++) {
                uint32_t kb2[4];
                LDSM_X4(kb2[0], kb2[1], kb2[2], kb2[3],
                        kbase + (uint32_t)(ks * 32 + j * (8 * FSTR * 2)));
                mma_bf16(S.f[j], qfh[ks], kb2);       // qh * kh
                mma_bf16(S.f[j], qfl[ks], kb2);       // ql * kh
                mma_bf16(S.f[j], qfh[ks], kb2 + 2);   // qh * kl
            }
        }

        // exp + per-thread partial row sums (quad shfl-reduce deferred to end)
#pragma unroll
        for (int j = 0; j < 8; j++) {
#pragma unroll
            for (int e = 0; e < 4; e++) S.f[j][e] = __expf(S.f[j][e]);
            lsum0 += S.f[j][0] + S.f[j][1];
            lsum1 += S.f[j][2] + S.f[j][3];
        }

        // Pack P hi/lo A-fragments in place over dead S registers:
        // hi[t] -> S.u[2t][0..3], lo[t] -> S.u[2t+1][0..3]
#pragma unroll
        for (int t = 0; t < 4; t++) {
            float a0 = S.f[2 * t][0], a1 = S.f[2 * t][1];
            float a2 = S.f[2 * t][2], a3 = S.f[2 * t][3];
            float b0 = S.f[2 * t + 1][0], b1 = S.f[2 * t + 1][1];
            float b2 = S.f[2 * t + 1][2], b3 = S.f[2 * t + 1][3];
            __nv_bfloat16 h0, l0, h1, l1, h2, l2, h3, l3;
            bsplit(a0, h0, l0); bsplit(a1, h1, l1);
            bsplit(a2, h2, l2); bsplit(a3, h3, l3);
            S.u[2 * t][0] = pk2(h0, h1);
            S.u[2 * t][1] = pk2(h2, h3);
            S.u[2 * t + 1][0] = pk2(l0, l1);
            S.u[2 * t + 1][1] = pk2(l2, l3);
            bsplit(b0, h0, l0); bsplit(b1, h1, l1);
            bsplit(b2, h2, l2); bsplit(b3, h3, l3);
            S.u[2 * t][2] = pk2(h0, h1);
            S.u[2 * t][3] = pk2(h2, h3);
            S.u[2 * t + 1][2] = pk2(l0, l1);
            S.u[2 * t + 1][3] = pk2(l2, l3);
        }

        // O += P V
#pragma unroll
        for (int t = 0; t < 4; t++) {
#pragma unroll
            for (int j = 0; j < 8; j++) {
                uint32_t vb2[4];
                LDSM_X4(vb2[0], vb2[1], vb2[2], vb2[3],
                        vbase + (uint32_t)(t * 32 + j * (8 * FSTR * 2)));
                mma_bf16(o[j], S.u[2 * t], vb2);          // ph * vh
                mma_bf16(o[j], S.u[2 * t + 1], vb2);      // pl * vh
                mma_bf16(o[j], S.u[2 * t], vb2 + 2);      // ph * vl
            }
        }
        __syncthreads();
    }

    // Deferred quad reduction of the row sums
    lsum0 += __shfl_xor_sync(0xffffffffu, lsum0, 1);
    lsum0 += __shfl_xor_sync(0xffffffffu, lsum0, 2);
    lsum1 += __shfl_xor_sync(0xffffffffu, lsum1, 1);
    lsum1 += __shfl_xor_sync(0xffffffffu, lsum1, 2);

    // Normalize + split-store to d_ohi/d_olo in [B, N, 768]
    const float inv0 = 1.0f / lsum0, inv1 = 1.0f / lsum1;
    const int row0 = qt * 128 + wid * 16 + r4;
#pragma unroll
    for (int j = 0; j < 8; j++) {
        int col = head * HD + j * 8 + q4 * 2;
        __nv_bfloat16 h0, l0, h1, l1;
        float f0 = o[j][0] * inv0, f1 = o[j][1] * inv0;
        bsplit(f0, h0, l0); bsplit(f1, h1, l1);
        size_t off = ((size_t)(b * SEQ + row0)) * DIMC + col;
        *(uint32_t*)(d_ohi + off) = pk2(h0, h1);
        *(uint32_t*)(d_olo + off) = pk2(l0, l1);
        float f2 = o[j][2] * inv1, f3 = o[j][3] * inv1;
        bsplit(f2, h0, l0); bsplit(f3, h1, l1);
        off = ((size_t)(b * SEQ + row0 + 8)) * DIMC + col;
        *(uint32_t*)(d_ohi + off) = pk2(h0, h1);
        *(uint32_t*)(d_olo + off) = pk2(l0, l1);
    }
}

// ---------------------------------------------------------------------------
extern "C" void kernel_launch(void* const* d_in, const int* in_sizes, int n_in,
                              void* d_out, int out_size)
{
    const float* x  = (const float*)d_in[0];
    const float* kk = (const float*)d_in[1];
    const float* vv = (const float*)d_in[2];
    const float* wq = (const float*)d_in[3];
    const float* wp = (const float*)d_in[4];
    const float* bp = (const float*)d_in[5];
    float* out = (float*)d_out;

    cudaFuncSetAttribute(gemm_mma, cudaFuncAttributeMaxDynamicSharedMemorySize, G_SMEM_BYTES);
    cudaFuncSetAttribute(flash_mma, cudaFuncAttributeMaxDynamicSharedMemorySize, F_SMEM_BYTES);

    const int n4_big = ROWS_TOT * DIMC / 4;   // 786432
    const int n4_w   = DIMC * DIMC / 4;       // 147456

    split_kernel<<<(n4_big + 255) / 256, 256>>>(x,  0, n4_big);
    split_kernel<<<(n4_w   + 255) / 256, 256>>>(wq, 1, n4_w);
    split_kernel<<<(n4_w   + 255) / 256, 256>>>(wp, 2, n4_w);
    split_kernel<<<(n4_big + 255) / 256, 256>>>(kk, 3, n4_big);
    vtrans_kernel<<<dim3(SEQ / 64, BATCH * HEADS), 256>>>(vv);

    gemm_mma<<<dim3(DIMC / 128, ROWS_TOT / 128), 256, G_SMEM_BYTES>>>(nullptr, nullptr, 0);
    flash_mma<<<dim3(SEQ / 128, HEADS, BATCH), 256, F_SMEM_BYTES>>>();
    gemm_mma<<<dim3(DIMC / 128, ROWS_TOT / 128), 256, G_SMEM_BYTES>>>(bp, out, 1);
}

// round 12
// speedup vs baseline: 1.5067x; 1.4304x over previous
// R11: resubmission of R10 (fp16 2-MMA scheme) after container infra failure.
#include <cuda_runtime.h>
#include <cuda_fp16.h>
#include <math.h>
#include <stdint.h>

#define DIMC   768
#define HEADS  12
#define HD     64
#define BATCH  2
#define SEQ    2048
#define ROWS_TOT (BATCH * SEQ)      // 4096
#define QSCALE 0.125f

// ---------------------------------------------------------------------------
// Scratch (__device__ globals; 16B-aligned). A-side operands: hi+lo fp16.
// B-side operands (K, V, weights): hi-only fp16.
// ---------------------------------------------------------------------------
__device__ __align__(16) __half d_xhi[ROWS_TOT * DIMC];
__device__ __align__(16) __half d_xlo[ROWS_TOT * DIMC];
__device__ __align__(16) __half d_wqh[DIMC * DIMC];
__device__ __align__(16) __half d_wph[DIMC * DIMC];
__device__ __align__(16) __half d_kh [BATCH * HEADS * SEQ * HD];
__device__ __align__(16) __half d_vth[BATCH * HEADS * HD * SEQ];   // [bh][d][j]
__device__ __align__(16) __half d_qhi[BATCH * HEADS * SEQ * HD];
__device__ __align__(16) __half d_qlo[BATCH * HEADS * SEQ * HD];
__device__ __align__(16) __half d_ohi[ROWS_TOT * DIMC];
__device__ __align__(16) __half d_olo[ROWS_TOT * DIMC];

// ---------------------------------------------------------------------------
// Helpers
// ---------------------------------------------------------------------------
__device__ __forceinline__ uint32_t su32(const void* p) {
    uint32_t a;
    asm("{ .reg .u64 t; cvta.to.shared.u64 t, %1; cvt.u32.u64 %0, t; }"
        : "=r"(a) : "l"(p));
    return a;
}

__device__ __forceinline__ void cp16(uint32_t dst, const void* src) {
    asm volatile("cp.async.cg.shared.global [%0], [%1], 16;" :: "r"(dst), "l"(src));
}
#define CP_COMMIT() asm volatile("cp.async.commit_group;" ::: "memory")
#define CP_WAIT1()  asm volatile("cp.async.wait_group 1;" ::: "memory")
#define CP_WAIT0()  asm volatile("cp.async.wait_group 0;" ::: "memory")

#define LDSM_X4(r0, r1, r2, r3, addr) \
    asm volatile("ldmatrix.sync.aligned.m8n8.x4.shared.b16 {%0,%1,%2,%3}, [%4];" \
                 : "=r"(r0), "=r"(r1), "=r"(r2), "=r"(r3) : "r"(addr))

__device__ __forceinline__ void hsplit(float x, __half& h, __half& l) {
    h = __float2half(x);
    l = __float2half(x - __half2float(h));
}

__device__ __forceinline__ uint32_t pk2(__half a, __half b) {
    __half2 t = __halves2half2(a, b);
    return *reinterpret_cast<uint32_t*>(&t);
}

// D += A @ B  (m16n8k16, fp16 in, f32 acc), row.col
__device__ __forceinline__ void mma_f16(float* c, const uint32_t* a, const uint32_t* b) {
    asm volatile(
        "mma.sync.aligned.m16n8k16.row.col.f32.f16.f16.f32 "
        "{%0,%1,%2,%3}, {%4,%5,%6,%7}, {%8,%9}, {%0,%1,%2,%3};"
        : "+f"(c[0]), "+f"(c[1]), "+f"(c[2]), "+f"(c[3])
        : "r"(a[0]), "r"(a[1]), "r"(a[2]), "r"(a[3]), "r"(b[0]), "r"(b[1]));
}

// ---------------------------------------------------------------------------
// Prep kernels
// which 0: x -> xhi+xlo ; 1: wq -> wqh (hi only) ; 2: wp -> wph ; 3: k -> kh
// ---------------------------------------------------------------------------
__global__ void split_kernel(const float* __restrict__ src, int which, int n4) {
    int i = blockIdx.x * blockDim.x + threadIdx.x;
    if (i >= n4) return;
    float4 v = ((const float4*)src)[i];
    float vv[4] = {v.x, v.y, v.z, v.w};
    if (which == 0) {
        __half h[4], l[4];
#pragma unroll
        for (int j = 0; j < 4; j++) hsplit(vv[j], h[j], l[j]);
        *(uint2*)(d_xhi + (size_t)i * 4) = make_uint2(pk2(h[0], h[1]), pk2(h[2], h[3]));
        *(uint2*)(d_xlo + (size_t)i * 4) = make_uint2(pk2(l[0], l[1]), pk2(l[2], l[3]));
    } else {
        __half* hi = (which == 1) ? d_wqh : (which == 2) ? d_wph : d_kh;
        __half h[4];
#pragma unroll
        for (int j = 0; j < 4; j++) h[j] = __float2half(vv[j]);
        *(uint2*)(hi + (size_t)i * 4) = make_uint2(pk2(h[0], h[1]), pk2(h[2], h[3]));
    }
}

// V transpose: v[bh][j][d] -> vt[bh][d][j] (hi only)
__global__ __launch_bounds__(256) void vtrans_kernel(const float* __restrict__ v) {
    __shared__ float t[64][65];
    int bh = blockIdx.y, j0 = blockIdx.x * 64;
    const float* src = v + ((size_t)bh * SEQ + j0) * HD;
    for (int idx = threadIdx.x; idx < 1024; idx += 256) {
        int r = idx >> 4, c4 = (idx & 15) * 4;
        float4 val = *(const float4*)(src + r * HD + c4);
        t[r][c4] = val.x; t[r][c4 + 1] = val.y;
        t[r][c4 + 2] = val.z; t[r][c4 + 3] = val.w;
    }
    __syncthreads();
    for (int idx = threadIdx.x; idx < 1024; idx += 256) {
        int d = idx >> 4, c4 = (idx & 15) * 4;
        __half h[4];
#pragma unroll
        for (int jj = 0; jj < 4; jj++) h[jj] = __float2half(t[c4 + jj][d]);
        size_t o = ((size_t)bh * HD + d) * SEQ + j0 + c4;
        *(uint2*)(d_vth + o) = make_uint2(pk2(h[0], h[1]), pk2(h[2], h[3]));
    }
}

// ---------------------------------------------------------------------------
// GEMM: C[4096x768] = A @ W^T. A = hi+lo fp16 (2 MMAs), W = hi fp16.
// BM=128 BN=128 BK=32; 8 warps = 4(m) x 2(n), warp tile 32x64.
// ---------------------------------------------------------------------------
#define GSTR 40
#define G_ARR_ELEM   (128 * GSTR)
#define G_STAGE_ELEM (3 * G_ARR_ELEM)
#define G_SMEM_BYTES (2 * G_STAGE_ELEM * 2)   // 61440

__global__ __launch_bounds__(256, 2)
void gemm_mma(const float* __restrict__ bias, float* __restrict__ outp, int mode)
{
    extern __shared__ __half sm[];
    const uint32_t sb = su32(sm);

    const int tid = threadIdx.x, lane = tid & 31, wid = tid >> 5;
    const int wm = wid & 3, wn = wid >> 2;
    const int r4 = lane >> 2, q4 = lane & 3;
    const int m0 = blockIdx.y * 128, n0 = blockIdx.x * 128;

    const __half* Ahg = (mode == 0) ? d_xhi : d_ohi;
    const __half* Alg = (mode == 0) ? d_xlo : d_olo;
    const __half* Bhg = (mode == 0) ? d_wqh : d_wph;

    auto issue = [&](int kb, int s) {
        const int k0 = kb * 32;
        const uint32_t so = sb + (uint32_t)(s * G_STAGE_ELEM) * 2;
        for (int id = tid; id < 512; id += 256) {
            int r = id >> 2, sg = id & 3;
            uint32_t d0 = so + (uint32_t)(r * GSTR + sg * 8) * 2;
            size_t ga = (size_t)(m0 + r) * DIMC + k0 + sg * 8;
            size_t gb = (size_t)(n0 + r) * DIMC + k0 + sg * 8;
            cp16(d0,                      Ahg + ga);
            cp16(d0 + G_ARR_ELEM * 2,     Alg + ga);
            cp16(d0 + 2 * G_ARR_ELEM * 2, Bhg + gb);
        }
    };

    float c[2][8][4];
#pragma unroll
    for (int i = 0; i < 2; i++)
#pragma unroll
        for (int j = 0; j < 8; j++)
#pragma unroll
            for (int e = 0; e < 4; e++) c[i][j][e] = 0.f;

    issue(0, 0);
    CP_COMMIT();

    const int NKB = DIMC / 32;   // 24
    for (int kb = 0; kb < NKB; kb++) {
        if (kb + 1 < NKB) {
            issue(kb + 1, (kb + 1) & 1);
            CP_COMMIT();
            CP_WAIT1();
        } else {
            CP_WAIT0();
        }
        __syncthreads();

        const __half* Ah = sm + (kb & 1) * G_STAGE_ELEM;
        const __half* Al = Ah + G_ARR_ELEM;
        const __half* Bh = Ah + 2 * G_ARR_ELEM;

#pragma unroll
        for (int ks = 0; ks < 2; ks++) {
            const int ca = ks * 16 + q4 * 2;
            uint32_t ah[2][4], al2[2][4];
#pragma unroll
            for (int i = 0; i < 2; i++) {
                int rb = wm * 32 + i * 16 + r4;
                ah[i][0] = *(const uint32_t*)(Ah + rb * GSTR + ca);
                ah[i][1] = *(const uint32_t*)(Ah + (rb + 8) * GSTR + ca);
                ah[i][2] = *(const uint32_t*)(Ah + rb * GSTR + ca + 8);
                ah[i][3] = *(const uint32_t*)(Ah + (rb + 8) * GSTR + ca + 8);
                al2[i][0] = *(const uint32_t*)(Al + rb * GSTR + ca);
                al2[i][1] = *(const uint32_t*)(Al + (rb + 8) * GSTR + ca);
                al2[i][2] = *(const uint32_t*)(Al + rb * GSTR + ca + 8);
                al2[i][3] = *(const uint32_t*)(Al + (rb + 8) * GSTR + ca + 8);
            }
#pragma unroll
            for (int j = 0; j < 8; j++) {
                int nb = wn * 64 + j * 8 + r4;
                uint32_t bh2[2];
                bh2[0] = *(const uint32_t*)(Bh + nb * GSTR + ca);
                bh2[1] = *(const uint32_t*)(Bh + nb * GSTR + ca + 8);
#pragma unroll
                for (int i = 0; i < 2; i++) {
                    mma_f16(c[i][j], ah[i], bh2);
                    mma_f16(c[i][j], al2[i], bh2);
                }
            }
        }
        __syncthreads();
    }

    // Epilogue
#pragma unroll
    for (int i = 0; i < 2; i++) {
        int mrow = m0 + wm * 32 + i * 16 + r4;
#pragma unroll
        for (int j = 0; j < 8; j++) {
            int col = n0 + wn * 64 + j * 8 + q4 * 2;
            if (mode == 0) {
                int head = col >> 6, d = col & 63;
#pragma unroll
                for (int h2 = 0; h2 < 2; h2++) {
                    int m = mrow + h2 * 8;
                    int b = m >> 11, seqq = m & 2047;
                    float f0 = c[i][j][h2 * 2] * QSCALE;
                    float f1 = c[i][j][h2 * 2 + 1] * QSCALE;
                    __half h0, l0, h1, l1;
                    hsplit(f0, h0, l0); hsplit(f1, h1, l1);
                    size_t off = ((size_t)(b * HEADS + head) * SEQ + seqq) * HD + d;
                    *(uint32_t*)(d_qhi + off) = pk2(h0, h1);
                    *(uint32_t*)(d_qlo + off) = pk2(l0, l1);
                }
            } else {
                float2 bv = *(const float2*)(bias + col);
#pragma unroll
                for (int h2 = 0; h2 < 2; h2++) {
                    int m = mrow + h2 * 8;
                    float2 v;
                    v.x = c[i][j][h2 * 2] + bv.x;
                    v.y = c[i][j][h2 * 2 + 1] + bv.y;
                    *(float2*)(outp + (size_t)m * DIMC + col) = v;
                }
            }
        }
    }
}

// ---------------------------------------------------------------------------
// Flash attention: fp16 2-MMA scheme. 1 CTA per (b,h,128-q tile); 8 warps x
// 16 q rows; 32 chunks of 64 keys. Q = hi+lo fragments in regs; K, V = hi only.
// ---------------------------------------------------------------------------
#define FSTR 72
#define F_ARR_ELEM   (64 * FSTR)
#define F_STAGE_ELEM (2 * F_ARR_ELEM)
#define F_SMEM_BYTES (2 * F_STAGE_ELEM * 2)   // 36864

__global__ __launch_bounds__(256, 2)
void flash_mma()
{
    extern __shared__ __half fsm[];
    const uint32_t sb = su32(fsm);

    const int tid = threadIdx.x, lane = tid & 31, wid = tid >> 5;
    const int r4 = lane >> 2, q4 = lane & 3;
    const int grp = lane >> 3, lrow = lane & 7;
    const int qt = blockIdx.x, head = blockIdx.y, b = blockIdx.z;
    const int bh = b * HEADS + head;

    const __half* khg = d_kh  + (size_t)bh * SEQ * HD;
    const __half* vhg = d_vth + (size_t)bh * HD * SEQ;

    auto issue = [&](int c, int s) {
        const uint32_t so = sb + (uint32_t)(s * F_STAGE_ELEM) * 2;
        const __half* kh = khg + (size_t)c * 64 * HD;
        const __half* vh = vhg + c * 64;
        for (int id = tid; id < 512; id += 256) {
            int r = id >> 3, sg = id & 7;
            uint32_t d0 = so + (uint32_t)(r * FSTR + sg * 8) * 2;
            cp16(d0,                  kh + r * HD + sg * 8);
            cp16(d0 + F_ARR_ELEM * 2, vh + (size_t)r * SEQ + sg * 8);
        }
    };

    issue(0, 0);
    CP_COMMIT();

    // Q fragments directly from gmem (once)
    uint32_t qfh[4][4], qfl[4][4];
    {
        const __half* qhg = d_qhi + ((size_t)bh * SEQ + qt * 128) * HD;
        const __half* qlg = d_qlo + ((size_t)bh * SEQ + qt * 128) * HD;
        const int rb = wid * 16 + r4;
#pragma unroll
        for (int ks = 0; ks < 4; ks++) {
            const int ca = ks * 16 + q4 * 2;
            qfh[ks][0] = *(const uint32_t*)(qhg + rb * HD + ca);
            qfh[ks][1] = *(const uint32_t*)(qhg + (rb + 8) * HD + ca);
            qfh[ks][2] = *(const uint32_t*)(qhg + rb * HD + ca + 8);
            qfh[ks][3] = *(const uint32_t*)(qhg + (rb + 8) * HD + ca + 8);
            qfl[ks][0] = *(const uint32_t*)(qlg + rb * HD + ca);
            qfl[ks][1] = *(const uint32_t*)(qlg + (rb + 8) * HD + ca);
            qfl[ks][2] = *(const uint32_t*)(qlg + rb * HD + ca + 8);
            qfl[ks][3] = *(const uint32_t*)(qlg + (rb + 8) * HD + ca + 8);
        }
    }

    float o[8][4];
#pragma unroll
    for (int j = 0; j < 8; j++)
#pragma unroll
        for (int e = 0; e < 4; e++) o[j][e] = 0.f;
    float lsum0 = 0.f, lsum1 = 0.f;

    // ldmatrix lane base: grp0 -> rows+0 col ca, grp1 -> rows+0 col ca+8,
    //                     grp2 -> rows+8 col ca, grp3 -> rows+8 col ca+8
    const uint32_t lbase = (uint32_t)((grp >> 1) * 8 + lrow) * FSTR * 2u + (grp & 1) * 16u;
    const uint32_t vbase_off = (uint32_t)F_ARR_ELEM * 2u + lbase;

    union { float f[8][4]; uint32_t u[8][4]; } S;

    const int NC = SEQ / 64;   // 32
    for (int c = 0; c < NC; c++) {
        if (c + 1 < NC) {
            issue(c + 1, (c + 1) & 1);
            CP_COMMIT();
            CP_WAIT1();
        } else {
            CP_WAIT0();
        }
        __syncthreads();

        const uint32_t stage = sb + (uint32_t)((c & 1) * F_STAGE_ELEM) * 2;
        const uint32_t kbase = stage + lbase;
        const uint32_t vbase = stage + vbase_off;

        // S = Q K^T  (one LDSM_X4 covers key tiles j=2jp and 2jp+1)
#pragma unroll
        for (int j = 0; j < 8; j++)
#pragma unroll
            for (int e = 0; e < 4; e++) S.f[j][e] = 0.f;

#pragma unroll
        for (int ks = 0; ks < 4; ks++) {
#pragma unroll
            for (int jp = 0; jp < 4; jp++) {
                uint32_t kb2[4];
                LDSM_X4(kb2[0], kb2[1], kb2[2], kb2[3],
                        kbase + (uint32_t)(jp * (16 * FSTR * 2) + ks * 32));
                mma_f16(S.f[2 * jp],     qfh[ks], kb2);
                mma_f16(S.f[2 * jp],     qfl[ks], kb2);
                mma_f16(S.f[2 * jp + 1], qfh[ks], kb2 + 2);
                mma_f16(S.f[2 * jp + 1], qfl[ks], kb2 + 2);
            }
        }

        // exp + per-thread partial row sums (quad shfl-reduce deferred)
#pragma unroll
        for (int j = 0; j < 8; j++) {
#pragma unroll
            for (int e = 0; e < 4; e++) S.f[j][e] = __expf(S.f[j][e]);
            lsum0 += S.f[j][0] + S.f[j][1];
            lsum1 += S.f[j][2] + S.f[j][3];
        }

        // Pack P hi/lo fp16 A-fragments in place over dead S registers:
        // hi[t] -> S.u[2t][0..3], lo[t] -> S.u[2t+1][0..3]
#pragma unroll
        for (int t = 0; t < 4; t++) {
            float a0 = S.f[2 * t][0], a1 = S.f[2 * t][1];
            float a2 = S.f[2 * t][2], a3 = S.f[2 * t][3];
            float b0 = S.f[2 * t + 1][0], b1 = S.f[2 * t + 1][1];
            float b2 = S.f[2 * t + 1][2], b3 = S.f[2 * t + 1][3];
            __half h0, l0, h1, l1, h2, l2, h3, l3;
            hsplit(a0, h0, l0); hsplit(a1, h1, l1);
            hsplit(a2, h2, l2); hsplit(a3, h3, l3);
            S.u[2 * t][0] = pk2(h0, h1);
            S.u[2 * t][1] = pk2(h2, h3);
            S.u[2 * t + 1][0] = pk2(l0, l1);
            S.u[2 * t + 1][1] = pk2(l2, l3);
            hsplit(b0, h0, l0); hsplit(b1, h1, l1);
            hsplit(b2, h2, l2); hsplit(b3, h3, l3);
            S.u[2 * t][2] = pk2(h0, h1);
            S.u[2 * t][3] = pk2(h2, h3);
            S.u[2 * t + 1][2] = pk2(l0, l1);
            S.u[2 * t + 1][3] = pk2(l2, l3);
        }

        // O += P V  (one LDSM_X4 covers d tiles j=2jp and 2jp+1)
#pragma unroll
        for (int t = 0; t < 4; t++) {
#pragma unroll
            for (int jp = 0; jp < 4; jp++) {
                uint32_t vb2[4];
                LDSM_X4(vb2[0], vb2[1], vb2[2], vb2[3],
                        vbase + (uint32_t)(jp * (16 * FSTR * 2) + t * 32));
                mma_f16(o[2 * jp],     S.u[2 * t],     vb2);
                mma_f16(o[2 * jp],     S.u[2 * t + 1], vb2);
                mma_f16(o[2 * jp + 1], S.u[2 * t],     vb2 + 2);
                mma_f16(o[2 * jp + 1], S.u[2 * t + 1], vb2 + 2);
            }
        }
        __syncthreads();
    }

    // Deferred quad reduction of the row sums
    lsum0 += __shfl_xor_sync(0xffffffffu, lsum0, 1);
    lsum0 += __shfl_xor_sync(0xffffffffu, lsum0, 2);
    lsum1 += __shfl_xor_sync(0xffffffffu, lsum1, 1);
    lsum1 += __shfl_xor_sync(0xffffffffu, lsum1, 2);

    // Normalize + split-store O (fp16 hi/lo) in [B, N, 768]
    const float inv0 = 1.0f / lsum0, inv1 = 1.0f / lsum1;
    const int row0 = qt * 128 + wid * 16 + r4;
#pragma unroll
    for (int j = 0; j < 8; j++) {
        int col = head * HD + j * 8 + q4 * 2;
        __half h0, l0, h1, l1;
        float f0 = o[j][0] * inv0, f1 = o[j][1] * inv0;
        hsplit(f0, h0, l0); hsplit(f1, h1, l1);
        size_t off = ((size_t)(b * SEQ + row0)) * DIMC + col;
        *(uint32_t*)(d_ohi + off) = pk2(h0, h1);
        *(uint32_t*)(d_olo + off) = pk2(l0, l1);
        float f2 = o[j][2] * inv1, f3 = o[j][3] * inv1;
        hsplit(f2, h0, l0); hsplit(f3, h1, l1);
        off = ((size_t)(b * SEQ + row0 + 8)) * DIMC + col;
        *(uint32_t*)(d_ohi + off) = pk2(h0, h1);
        *(uint32_t*)(d_olo + off) = pk2(l0, l1);
    }
}

// ---------------------------------------------------------------------------
extern "C" void kernel_launch(void* const* d_in, const int* in_sizes, int n_in,
                              void* d_out, int out_size)
{
    const float* x  = (const float*)d_in[0];
    const float* kk = (const float*)d_in[1];
    const float* vv = (const float*)d_in[2];
    const float* wq = (const float*)d_in[3];
    const float* wp = (const float*)d_in[4];
    const float* bp = (const float*)d_in[5];
    float* out = (float*)d_out;

    cudaFuncSetAttribute(gemm_mma, cudaFuncAttributeMaxDynamicSharedMemorySize, G_SMEM_BYTES);
    cudaFuncSetAttribute(flash_mma, cudaFuncAttributeMaxDynamicSharedMemorySize, F_SMEM_BYTES);

    const int n4_big = ROWS_TOT * DIMC / 4;   // 786432
    const int n4_w   = DIMC * DIMC / 4;       // 147456

    split_kernel<<<(n4_big + 255) / 256, 256>>>(x,  0, n4_big);
    split_kernel<<<(n4_w   + 255) / 256, 256>>>(wq, 1, n4_w);
    split_kernel<<<(n4_w   + 255) / 256, 256>>>(wp, 2, n4_w);
    split_kernel<<<(n4_big + 255) / 256, 256>>>(kk, 3, n4_big);
    vtrans_kernel<<<dim3(SEQ / 64, BATCH * HEADS), 256>>>(vv);

    gemm_mma<<<dim3(DIMC / 128, ROWS_TOT / 128), 256, G_SMEM_BYTES>>>(nullptr, nullptr, 0);
    flash_mma<<<dim3(SEQ / 128, HEADS, BATCH), 256, F_SMEM_BYTES>>>();
    gemm_mma<<<dim3(DIMC / 128, ROWS_TOT / 128), 256, G_SMEM_BYTES>>>(bp, out, 1);
}

// round 15
// speedup vs baseline: 2.5235x; 1.6749x over previous
// R13: full single-fp16 pipeline (1 MMA per tile everywhere), fp32 accumulate.
#include <cuda_runtime.h>
#include <cuda_fp16.h>
#include <math.h>
#include <stdint.h>

#define DIMC   768
#define HEADS  12
#define HD     64
#define BATCH  2
#define SEQ    2048
#define ROWS_TOT (BATCH * SEQ)      // 4096
#define QSCALE 0.125f

// ---------------------------------------------------------------------------
// Scratch (__device__ globals; 16B-aligned). All operands single fp16.
// ---------------------------------------------------------------------------
__device__ __align__(16) __half d_xh [ROWS_TOT * DIMC];
__device__ __align__(16) __half d_wqh[DIMC * DIMC];
__device__ __align__(16) __half d_wph[DIMC * DIMC];
__device__ __align__(16) __half d_kh [BATCH * HEADS * SEQ * HD];
__device__ __align__(16) __half d_vth[BATCH * HEADS * HD * SEQ];   // [bh][d][j]
__device__ __align__(16) __half d_qh [BATCH * HEADS * SEQ * HD];
__device__ __align__(16) __half d_oh [ROWS_TOT * DIMC];

// ---------------------------------------------------------------------------
// Helpers
// ---------------------------------------------------------------------------
__device__ __forceinline__ uint32_t su32(const void* p) {
    uint32_t a;
    asm("{ .reg .u64 t; cvta.to.shared.u64 t, %1; cvt.u32.u64 %0, t; }"
        : "=r"(a) : "l"(p));
    return a;
}

__device__ __forceinline__ void cp16(uint32_t dst, const void* src) {
    asm volatile("cp.async.cg.shared.global [%0], [%1], 16;" :: "r"(dst), "l"(src));
}
#define CP_COMMIT() asm volatile("cp.async.commit_group;" ::: "memory")
#define CP_WAIT1()  asm volatile("cp.async.wait_group 1;" ::: "memory")
#define CP_WAIT0()  asm volatile("cp.async.wait_group 0;" ::: "memory")

#define LDSM_X4(r0, r1, r2, r3, addr) \
    asm volatile("ldmatrix.sync.aligned.m8n8.x4.shared.b16 {%0,%1,%2,%3}, [%4];" \
                 : "=r"(r0), "=r"(r1), "=r"(r2), "=r"(r3) : "r"(addr))

__device__ __forceinline__ uint32_t pk2(__half a, __half b) {
    __half2 t = __halves2half2(a, b);
    return *reinterpret_cast<uint32_t*>(&t);
}

__device__ __forceinline__ uint32_t pk2f(float a, float b) {
    return pk2(__float2half(a), __float2half(b));
}

// D += A @ B  (m16n8k16, fp16 in, f32 acc), row.col
__device__ __forceinline__ void mma_f16(float* c, const uint32_t* a, const uint32_t* b) {
    asm volatile(
        "mma.sync.aligned.m16n8k16.row.col.f32.f16.f16.f32 "
        "{%0,%1,%2,%3}, {%4,%5,%6,%7}, {%8,%9}, {%0,%1,%2,%3};"
        : "+f"(c[0]), "+f"(c[1]), "+f"(c[2]), "+f"(c[3])
        : "r"(a[0]), "r"(a[1]), "r"(a[2]), "r"(a[3]), "r"(b[0]), "r"(b[1]));
}

// ---------------------------------------------------------------------------
// Prep: one fused fp32 -> fp16 convert for x, k, wq, wp; separate V transpose.
// Segment layout (float4 units): [0,X4) x ; [X4,2*X4) k ; then wq ; then wp.
// ---------------------------------------------------------------------------
#define X4  (ROWS_TOT * DIMC / 4)    // 786432
#define W4  (DIMC * DIMC / 4)        // 147456
#define TOT4 (2 * X4 + 2 * W4)       // 1867776

__global__ void cvt_all(const float* __restrict__ x, const float* __restrict__ k,
                        const float* __restrict__ wq, const float* __restrict__ wp) {
    int i = blockIdx.x * blockDim.x + threadIdx.x;
    if (i >= TOT4) return;
    const float* src;
    __half* dst;
    int off;
    if (i < X4)             { src = x;  dst = d_xh;  off = i; }
    else if (i < 2 * X4)    { src = k;  dst = d_kh;  off = i - X4; }
    else if (i < 2 * X4 + W4) { src = wq; dst = d_wqh; off = i - 2 * X4; }
    else                    { src = wp; dst = d_wph; off = i - 2 * X4 - W4; }
    float4 v = ((const float4*)src)[off];
    *(uint2*)(dst + (size_t)off * 4) = make_uint2(pk2f(v.x, v.y), pk2f(v.z, v.w));
}

// V transpose: v[bh][j][d] -> vt[bh][d][j]
__global__ __launch_bounds__(256) void vtrans_kernel(const float* __restrict__ v) {
    __shared__ float t[64][65];
    int bh = blockIdx.y, j0 = blockIdx.x * 64;
    const float* src = v + ((size_t)bh * SEQ + j0) * HD;
    for (int idx = threadIdx.x; idx < 1024; idx += 256) {
        int r = idx >> 4, c4 = (idx & 15) * 4;
        float4 val = *(const float4*)(src + r * HD + c4);
        t[r][c4] = val.x; t[r][c4 + 1] = val.y;
        t[r][c4 + 2] = val.z; t[r][c4 + 3] = val.w;
    }
    __syncthreads();
    for (int idx = threadIdx.x; idx < 1024; idx += 256) {
        int d = idx >> 4, c4 = (idx & 15) * 4;
        size_t o = ((size_t)bh * HD + d) * SEQ + j0 + c4;
        *(uint2*)(d_vth + o) = make_uint2(pk2f(t[c4][d], t[c4 + 1][d]),
                                          pk2f(t[c4 + 2][d], t[c4 + 3][d]));
    }
}

// ---------------------------------------------------------------------------
// GEMM: C[4096x768] = A @ W^T. Single fp16 operands, 1 MMA per tile.
// BM=128 BN=128 BK=32; 8 warps = 4(m) x 2(n), warp tile 32x64.
// ---------------------------------------------------------------------------
#define GSTR 40
#define G_ARR_ELEM   (128 * GSTR)
#define G_STAGE_ELEM (2 * G_ARR_ELEM)
#define G_SMEM_BYTES (2 * G_STAGE_ELEM * 2)   // 40960

__global__ __launch_bounds__(256, 2)
void gemm_mma(const float* __restrict__ bias, float* __restrict__ outp, int mode)
{
    extern __shared__ __half sm[];
    const uint32_t sb = su32(sm);

    const int tid = threadIdx.x, lane = tid & 31, wid = tid >> 5;
    const int wm = wid & 3, wn = wid >> 2;
    const int r4 = lane >> 2, q4 = lane & 3;
    const int m0 = blockIdx.y * 128, n0 = blockIdx.x * 128;

    const __half* Ahg = (mode == 0) ? d_xh : d_oh;
    const __half* Bhg = (mode == 0) ? d_wqh : d_wph;

    auto issue = [&](int kb, int s) {
        const int k0 = kb * 32;
        const uint32_t so = sb + (uint32_t)(s * G_STAGE_ELEM) * 2;
        for (int id = tid; id < 512; id += 256) {
            int r = id >> 2, sg = id & 3;
            uint32_t d0 = so + (uint32_t)(r * GSTR + sg * 8) * 2;
            cp16(d0,                  Ahg + (size_t)(m0 + r) * DIMC + k0 + sg * 8);
            cp16(d0 + G_ARR_ELEM * 2, Bhg + (size_t)(n0 + r) * DIMC + k0 + sg * 8);
        }
    };

    float c[2][8][4];
#pragma unroll
    for (int i = 0; i < 2; i++)
#pragma unroll
        for (int j = 0; j < 8; j++)
#pragma unroll
            for (int e = 0; e < 4; e++) c[i][j][e] = 0.f;

    issue(0, 0);
    CP_COMMIT();

    const int NKB = DIMC / 32;   // 24
    for (int kb = 0; kb < NKB; kb++) {
        if (kb + 1 < NKB) {
            issue(kb + 1, (kb + 1) & 1);
            CP_COMMIT();
            CP_WAIT1();
        } else {
            CP_WAIT0();
        }
        __syncthreads();

        const __half* Ah = sm + (kb & 1) * G_STAGE_ELEM;
        const __half* Bh = Ah + G_ARR_ELEM;

#pragma unroll
        for (int ks = 0; ks < 2; ks++) {
            const int ca = ks * 16 + q4 * 2;
            uint32_t ah[2][4];
#pragma unroll
            for (int i = 0; i < 2; i++) {
                int rb = wm * 32 + i * 16 + r4;
                ah[i][0] = *(const uint32_t*)(Ah + rb * GSTR + ca);
                ah[i][1] = *(const uint32_t*)(Ah + (rb + 8) * GSTR + ca);
                ah[i][2] = *(const uint32_t*)(Ah + rb * GSTR + ca + 8);
                ah[i][3] = *(const uint32_t*)(Ah + (rb + 8) * GSTR + ca + 8);
            }
#pragma unroll
            for (int j = 0; j < 8; j++) {
                int nb = wn * 64 + j * 8 + r4;
                uint32_t bh2[2];
                bh2[0] = *(const uint32_t*)(Bh + nb * GSTR + ca);
                bh2[1] = *(const uint32_t*)(Bh + nb * GSTR + ca + 8);
                mma_f16(c[0][j], ah[0], bh2);
                mma_f16(c[1][j], ah[1], bh2);
            }
        }
        __syncthreads();
    }

    // Epilogue
#pragma unroll
    for (int i = 0; i < 2; i++) {
        int mrow = m0 + wm * 32 + i * 16 + r4;
#pragma unroll
        for (int j = 0; j < 8; j++) {
            int col = n0 + wn * 64 + j * 8 + q4 * 2;
            if (mode == 0) {
                int head = col >> 6, d = col & 63;
#pragma unroll
                for (int h2 = 0; h2 < 2; h2++) {
                    int m = mrow + h2 * 8;
                    int b = m >> 11, seqq = m & 2047;
                    size_t off = ((size_t)(b * HEADS + head) * SEQ + seqq) * HD + d;
                    *(uint32_t*)(d_qh + off) =
                        pk2f(c[i][j][h2 * 2] * QSCALE, c[i][j][h2 * 2 + 1] * QSCALE);
                }
            } else {
                float2 bv = *(const float2*)(bias + col);
#pragma unroll
                for (int h2 = 0; h2 < 2; h2++) {
                    int m = mrow + h2 * 8;
                    float2 v;
                    v.x = c[i][j][h2 * 2] + bv.x;
                    v.y = c[i][j][h2 * 2 + 1] + bv.y;
                    *(float2*)(outp + (size_t)m * DIMC + col) = v;
                }
            }
        }
    }
}

// ---------------------------------------------------------------------------
// Flash attention: single fp16, 1 MMA per tile. 1 CTA per (b,h,128-q tile);
// 8 warps x 16 q rows; 32 chunks of 64 keys. Max-free softmax, O in regs.
// ---------------------------------------------------------------------------
#define FSTR 72
#define F_ARR_ELEM   (64 * FSTR)
#define F_STAGE_ELEM (2 * F_ARR_ELEM)
#define F_SMEM_BYTES (2 * F_STAGE_ELEM * 2)   // 36864

__global__ __launch_bounds__(256, 2)
void flash_mma()
{
    extern __shared__ __half fsm[];
    const uint32_t sb = su32(fsm);

    const int tid = threadIdx.x, lane = tid & 31, wid = tid >> 5;
    const int r4 = lane >> 2, q4 = lane & 3;
    const int grp = lane >> 3, lrow = lane & 7;
    const int qt = blockIdx.x, head = blockIdx.y, b = blockIdx.z;
    const int bh = b * HEADS + head;

    const __half* khg = d_kh  + (size_t)bh * SEQ * HD;
    const __half* vhg = d_vth + (size_t)bh * HD * SEQ;

    auto issue = [&](int c, int s) {
        const uint32_t so = sb + (uint32_t)(s * F_STAGE_ELEM) * 2;
        const __half* kh = khg + (size_t)c * 64 * HD;
        const __half* vh = vhg + c * 64;
        for (int id = tid; id < 512; id += 256) {
            int r = id >> 3, sg = id & 7;
            uint32_t d0 = so + (uint32_t)(r * FSTR + sg * 8) * 2;
            cp16(d0,                  kh + r * HD + sg * 8);
            cp16(d0 + F_ARR_ELEM * 2, vh + (size_t)r * SEQ + sg * 8);
        }
    };

    issue(0, 0);
    CP_COMMIT();

    // Q fragments directly from gmem (once)
    uint32_t qfh[4][4];
    {
        const __half* qhg = d_qh + ((size_t)bh * SEQ + qt * 128) * HD;
        const int rb = wid * 16 + r4;
#pragma unroll
        for (int ks = 0; ks < 4; ks++) {
            const int ca = ks * 16 + q4 * 2;
            qfh[ks][0] = *(const uint32_t*)(qhg + rb * HD + ca);
            qfh[ks][1] = *(const uint32_t*)(qhg + (rb + 8) * HD + ca);
            qfh[ks][2] = *(const uint32_t*)(qhg + rb * HD + ca + 8);
            qfh[ks][3] = *(const uint32_t*)(qhg + (rb + 8) * HD + ca + 8);
        }
    }

    float o[8][4];
#pragma unroll
    for (int j = 0; j < 8; j++)
#pragma unroll
        for (int e = 0; e < 4; e++) o[j][e] = 0.f;
    float lsum0 = 0.f, lsum1 = 0.f;

    // ldmatrix lane base: grp0 -> rows+0 col ca, grp1 -> rows+0 col ca+8,
    //                     grp2 -> rows+8 col ca, grp3 -> rows+8 col ca+8
    const uint32_t lbase = (uint32_t)((grp >> 1) * 8 + lrow) * FSTR * 2u + (grp & 1) * 16u;
    const uint32_t vbase_off = (uint32_t)F_ARR_ELEM * 2u + lbase;

    union { float f[8][4]; uint32_t u[8][4]; } S;

    const int NC = SEQ / 64;   // 32
    for (int c = 0; c < NC; c++) {
        if (c + 1 < NC) {
            issue(c + 1, (c + 1) & 1);
            CP_COMMIT();
            CP_WAIT1();
        } else {
            CP_WAIT0();
        }
        __syncthreads();

        const uint32_t stage = sb + (uint32_t)((c & 1) * F_STAGE_ELEM) * 2;
        const uint32_t kbase = stage + lbase;
        const uint32_t vbase = stage + vbase_off;

        // S = Q K^T  (one LDSM_X4 covers key tiles j=2jp and 2jp+1)
#pragma unroll
        for (int j = 0; j < 8; j++)
#pragma unroll
            for (int e = 0; e < 4; e++) S.f[j][e] = 0.f;

#pragma unroll
        for (int ks = 0; ks < 4; ks++) {
#pragma unroll
            for (int jp = 0; jp < 4; jp++) {
                uint32_t kb2[4];
                LDSM_X4(kb2[0], kb2[1], kb2[2], kb2[3],
                        kbase + (uint32_t)(jp * (16 * FSTR * 2) + ks * 32));
                mma_f16(S.f[2 * jp],     qfh[ks], kb2);
                mma_f16(S.f[2 * jp + 1], qfh[ks], kb2 + 2);
            }
        }

        // exp + per-thread partial row sums (quad shfl-reduce deferred)
#pragma unroll
        for (int j = 0; j < 8; j++) {
#pragma unroll
            for (int e = 0; e < 4; e++) S.f[j][e] = __expf(S.f[j][e]);
            lsum0 += S.f[j][0] + S.f[j][1];
            lsum1 += S.f[j][2] + S.f[j][3];
        }

        // Pack P fp16 A-fragments in place: tile pair (2t,2t+1) -> S.u[2t][0..3]
#pragma unroll
        for (int t = 0; t < 4; t++) {
            float a0 = S.f[2 * t][0], a1 = S.f[2 * t][1];
            float a2 = S.f[2 * t][2], a3 = S.f[2 * t][3];
            float b0 = S.f[2 * t + 1][0], b1 = S.f[2 * t + 1][1];
            float b2 = S.f[2 * t + 1][2], b3 = S.f[2 * t + 1][3];
            S.u[2 * t][0] = pk2f(a0, a1);
            S.u[2 * t][1] = pk2f(a2, a3);
            S.u[2 * t][2] = pk2f(b0, b1);
            S.u[2 * t][3] = pk2f(b2, b3);
        }

        // O += P V  (one LDSM_X4 covers d tiles j=2jp and 2jp+1)
#pragma unroll
        for (int t = 0; t < 4; t++) {
#pragma unroll
            for (int jp = 0; jp < 4; jp++) {
                uint32_t vb2[4];
                LDSM_X4(vb2[0], vb2[1], vb2[2], vb2[3],
                        vbase + (uint32_t)(jp * (16 * FSTR * 2) + t * 32));
                mma_f16(o[2 * jp],     S.u[2 * t], vb2);
                mma_f16(o[2 * jp + 1], S.u[2 * t], vb2 + 2);
            }
        }
        __syncthreads();
    }

    // Deferred quad reduction of the row sums
    lsum0 += __shfl_xor_sync(0xffffffffu, lsum0, 1);
    lsum0 += __shfl_xor_sync(0xffffffffu, lsum0, 2);
    lsum1 += __shfl_xor_sync(0xffffffffu, lsum1, 1);
    lsum1 += __shfl_xor_sync(0xffffffffu, lsum1, 2);

    // Normalize + store O (single fp16) in [B, N, 768]
    const float inv0 = 1.0f / lsum0, inv1 = 1.0f / lsum1;
    const int row0 = qt * 128 + wid * 16 + r4;
#pragma unroll
    for (int j = 0; j < 8; j++) {
        int col = head * HD + j * 8 + q4 * 2;
        size_t off = ((size_t)(b * SEQ + row0)) * DIMC + col;
        *(uint32_t*)(d_oh + off) = pk2f(o[j][0] * inv0, o[j][1] * inv0);
        off = ((size_t)(b * SEQ + row0 + 8)) * DIMC + col;
        *(uint32_t*)(d_oh + off) = pk2f(o[j][2] * inv1, o[j][3] * inv1);
    }
}

// ---------------------------------------------------------------------------
extern "C" void kernel_launch(void* const* d_in, const int* in_sizes, int n_in,
                              void* d_out, int out_size)
{
    const float* x  = (const float*)d_in[0];
    const float* kk = (const float*)d_in[1];
    const float* vv = (const float*)d_in[2];
    const float* wq = (const float*)d_in[3];
    const float* wp = (const float*)d_in[4];
    const float* bp = (const float*)d_in[5];
    float* out = (float*)d_out;

    cudaFuncSetAttribute(gemm_mma, cudaFuncAttributeMaxDynamicSharedMemorySize, G_SMEM_BYTES);
    cudaFuncSetAttribute(flash_mma, cudaFuncAttributeMaxDynamicSharedMemorySize, F_SMEM_BYTES);

    cvt_all<<<(TOT4 + 255) / 256, 256>>>(x, kk, wq, wp);
    vtrans_kernel<<<dim3(SEQ / 64, BATCH * HEADS), 256>>>(vv);

    gemm_mma<<<dim3(DIMC / 128, ROWS_TOT / 128), 256, G_SMEM_BYTES>>>(nullptr, nullptr, 0);
    flash_mma<<<dim3(SEQ / 128, HEADS, BATCH), 256, F_SMEM_BYTES>>>();
    gemm_mma<<<dim3(DIMC / 128, ROWS_TOT / 128), 256, G_SMEM_BYTES>>>(bp, out, 1);
}